// round 1
// baseline (speedup 1.0000x reference)
#include <cuda_runtime.h>

#define SSCALE 1.6666666666666667f

__device__ __forceinline__ float ssilu(float x) {
    float e = __expf(-x);
    return SSCALE * __fdividef(x, 1.0f + e);
}

#define E_MAX 700000
#define N_MAX 40000

__device__ float g_xdown[(size_t)E_MAX * 16];
__device__ float g_xe[(size_t)E_MAX * 16];
__device__ float g_h[(size_t)N_MAX * 128];

// ---------------- K0: zero scratch ----------------
__global__ void k_zero(int n_xe4, int n_h4) {
    int i = blockIdx.x * blockDim.x + threadIdx.x;
    int stride = gridDim.x * blockDim.x;
    float4 z = make_float4(0.f, 0.f, 0.f, 0.f);
    for (int r = i; r < n_xe4; r += stride) ((float4*)g_xe)[r] = z;
    for (int r = i; r < n_h4; r += stride) ((float4*)g_h)[r] = z;
}

// ---------------- K1: edge dense + down projection ----------------
// x_ba = ssilu(m @ W_ba) * (rbf @ W_rbf)   [E,128]
// g_xdown = x_ba @ W_down                  [E,16]
// Tiling: 32 edges per tile, 256 threads = 8 edge-groups x 32 j-groups.
// Each thread: 4 edges x 4 outputs.
__global__ __launch_bounds__(256, 2) void k_edge_down(
    const float* __restrict__ m, const float* __restrict__ rbf,
    const float* __restrict__ Wba, const float* __restrict__ Wrbf,
    const float* __restrict__ Wdown, int E)
{
    extern __shared__ float sm_[];
    float* sWba  = sm_;                 // 16384  [k][j]
    float* sWrbf = sWba + 16384;        // 2048   [s][j]
    float* sWdT  = sWrbf + 2048;        // 16*132 [d][j] (transposed, padded)
    float* sM    = sWdT + 16 * 132;     // 32*132 [e][k] (padded)
    float* sRbf  = sM + 32 * 132;       // 512    [e][s]

    int tid = threadIdx.x;
    for (int i = tid; i < 16384; i += 256) sWba[i] = Wba[i];
    for (int i = tid; i < 2048; i += 256) sWrbf[i] = Wrbf[i];
    for (int i = tid; i < 2048; i += 256) {
        int d = i >> 7, j = i & 127;
        sWdT[d * 132 + j] = Wdown[j * 16 + d];
    }
    __syncthreads();

    int ntiles = (E + 31) >> 5;
    int jt = tid & 31, et = tid >> 5;

    for (int tile = blockIdx.x; tile < ntiles; tile += gridDim.x) {
        int e0 = tile << 5;
        // load m tile [32][128] as float4
        for (int r = tid; r < 1024; r += 256) {
            int e = r >> 5, c = r & 31;
            float4 v = make_float4(0.f, 0.f, 0.f, 0.f);
            if (e0 + e < E) v = ((const float4*)(m + (size_t)(e0 + e) * 128))[c];
            *((float4*)&sM[e * 132 + c * 4]) = v;
        }
        // load rbf tile [32][16]
        for (int r = tid; r < 128; r += 256) {
            int e = r >> 2, c = r & 3;
            float4 v = make_float4(0.f, 0.f, 0.f, 0.f);
            if (e0 + e < E) v = ((const float4*)(rbf + (size_t)(e0 + e) * 16))[c];
            *((float4*)&sRbf[e * 16 + c * 4]) = v;
        }
        __syncthreads();

        float acc[4][4];
        #pragma unroll
        for (int i = 0; i < 4; i++) {
            acc[i][0] = 0.f; acc[i][1] = 0.f; acc[i][2] = 0.f; acc[i][3] = 0.f;
        }

        #pragma unroll 4
        for (int k4 = 0; k4 < 32; k4++) {
            float4 mv[4];
            #pragma unroll
            for (int i = 0; i < 4; i++)
                mv[i] = *((float4*)&sM[(et * 4 + i) * 132 + k4 * 4]);
            #pragma unroll
            for (int kk = 0; kk < 4; kk++) {
                float4 w = *((float4*)&sWba[(k4 * 4 + kk) * 128 + jt * 4]);
                #pragma unroll
                for (int i = 0; i < 4; i++) {
                    float mk = (kk == 0) ? mv[i].x : (kk == 1) ? mv[i].y
                             : (kk == 2) ? mv[i].z : mv[i].w;
                    acc[i][0] += mk * w.x;
                    acc[i][1] += mk * w.y;
                    acc[i][2] += mk * w.z;
                    acc[i][3] += mk * w.w;
                }
            }
        }

        // rbf modulation weights: rw = rbf @ W_rbf
        float rw[4][4];
        #pragma unroll
        for (int i = 0; i < 4; i++) {
            rw[i][0] = 0.f; rw[i][1] = 0.f; rw[i][2] = 0.f; rw[i][3] = 0.f;
        }
        #pragma unroll
        for (int s = 0; s < 16; s++) {
            float4 w = *((float4*)&sWrbf[s * 128 + jt * 4]);
            #pragma unroll
            for (int i = 0; i < 4; i++) {
                float rv = sRbf[(et * 4 + i) * 16 + s];
                rw[i][0] += rv * w.x;
                rw[i][1] += rv * w.y;
                rw[i][2] += rv * w.z;
                rw[i][3] += rv * w.w;
            }
        }

        __syncthreads();   // everyone done reading sM (m values)
        // write x_ba into sM (reuse)
        #pragma unroll
        for (int i = 0; i < 4; i++) {
            float4 v;
            v.x = ssilu(acc[i][0]) * rw[i][0];
            v.y = ssilu(acc[i][1]) * rw[i][1];
            v.z = ssilu(acc[i][2]) * rw[i][2];
            v.w = ssilu(acc[i][3]) * rw[i][3];
            *((float4*)&sM[(et * 4 + i) * 132 + jt * 4]) = v;
        }
        __syncthreads();

        // down projection: 512 outputs (32 edges x 16 d), 2 per thread
        #pragma unroll
        for (int o = tid; o < 512; o += 256) {
            int e = o >> 4, dd = o & 15;
            float s = 0.f;
            #pragma unroll
            for (int j4 = 0; j4 < 32; j4++) {
                float4 x = *((float4*)&sM[e * 132 + j4 * 4]);
                float4 w = *((float4*)&sWdT[dd * 132 + j4 * 4]);
                s += x.x * w.x + x.y * w.y + x.z * w.z + x.w * w.w;
            }
            if (e0 + e < E) g_xdown[(size_t)(e0 + e) * 16 + dd] = s;
        }
        __syncthreads();  // protect sM before next tile's load
    }
}

// ---------------- K2: triplet gather/modulate/scatter ----------------
// x_t = g_xdown[id3_ba] * (cbf @ W_cbf);  g_xe[id3_ca] += x_t  (atomic)
__global__ __launch_bounds__(256) void k_triplet(
    const float* __restrict__ cbf,
    const int* __restrict__ ba, const int* __restrict__ ca,
    const float* __restrict__ Wcbf, int T)
{
    __shared__ float sW[256];   // [s][d]
    int tid = threadIdx.x;
    sW[tid] = Wcbf[tid];
    __syncthreads();

    int t = blockIdx.x * 256 + tid;
    if (t >= T) return;

    float4 c4[4];
    const float4* cp = (const float4*)(cbf + (size_t)t * 16);
    c4[0] = cp[0]; c4[1] = cp[1]; c4[2] = cp[2]; c4[3] = cp[3];
    const float* c = (const float*)c4;

    float4 o[4];
    o[0] = make_float4(0.f, 0.f, 0.f, 0.f); o[1] = o[0]; o[2] = o[0]; o[3] = o[0];
    #pragma unroll
    for (int s = 0; s < 16; s++) {
        float cs = c[s];
        #pragma unroll
        for (int q = 0; q < 4; q++) {
            float4 w = *((const float4*)&sW[s * 16 + q * 4]);
            o[q].x += cs * w.x; o[q].y += cs * w.y;
            o[q].z += cs * w.z; o[q].w += cs * w.w;
        }
    }

    int b = ba[t], a = ca[t];
    const float4* xd = (const float4*)(g_xdown + (size_t)b * 16);
    float* dst = g_xe + (size_t)a * 16;
    #pragma unroll
    for (int q = 0; q < 4; q++) {
        float4 x = xd[q];
        float vx = o[q].x * x.x, vy = o[q].y * x.y,
              vz = o[q].z * x.z, vw = o[q].w * x.w;
        asm volatile("red.global.add.v4.f32 [%0], {%1,%2,%3,%4};"
                     :: "l"(dst + q * 4), "f"(vx), "f"(vy), "f"(vz), "f"(vw)
                     : "memory");
    }
}

// ---------------- K3: edge up-projection + atom scatter ----------------
// m_new = m + ssilu(g_xe @ W_up); g_h[idx_t] += m_new * (rbf @ W_rbf_atom)
// 32 edges per tile, 256 threads = 8 edge-slots x 32 lanes; 4 edges/thread, 4 j/thread.
__global__ __launch_bounds__(256) void k_edge_up(
    const float* __restrict__ m, const float* __restrict__ rbf,
    const int* __restrict__ idxt,
    const float* __restrict__ Wup, const float* __restrict__ Wra, int E)
{
    __shared__ float sWup[2048];   // [d][j]
    __shared__ float sWra[2048];   // [s][j]
    __shared__ float sXe[512];     // [32][16]
    __shared__ float sRbf[512];    // [32][16]
    __shared__ int   sIdx[32];

    int tid = threadIdx.x;
    for (int i = tid; i < 2048; i += 256) { sWup[i] = Wup[i]; sWra[i] = Wra[i]; }

    int ntiles = (E + 31) >> 5;
    int lane = tid & 31, et = tid >> 5;

    for (int tile = blockIdx.x; tile < ntiles; tile += gridDim.x) {
        int e0 = tile << 5;
        __syncthreads();  // previous tile's readers done
        for (int r = tid; r < 128; r += 256) {
            int e = r >> 2, cq = r & 3;
            float4 vx = make_float4(0.f, 0.f, 0.f, 0.f), vr = vx;
            if (e0 + e < E) {
                vx = ((const float4*)(g_xe + (size_t)(e0 + e) * 16))[cq];
                vr = ((const float4*)(rbf + (size_t)(e0 + e) * 16))[cq];
            }
            *((float4*)&sXe[e * 16 + cq * 4]) = vx;
            *((float4*)&sRbf[e * 16 + cq * 4]) = vr;
        }
        if (tid < 32) sIdx[tid] = (e0 + tid < E) ? idxt[e0 + tid] : -1;
        __syncthreads();

        float u[4][4], rr[4][4];
        #pragma unroll
        for (int i = 0; i < 4; i++) {
            u[i][0] = u[i][1] = u[i][2] = u[i][3] = 0.f;
            rr[i][0] = rr[i][1] = rr[i][2] = rr[i][3] = 0.f;
        }
        #pragma unroll
        for (int d = 0; d < 16; d++) {
            float4 wu = *((float4*)&sWup[d * 128 + lane * 4]);
            float4 wr = *((float4*)&sWra[d * 128 + lane * 4]);
            #pragma unroll
            for (int i = 0; i < 4; i++) {
                int e = et + 8 * i;
                float xv = sXe[e * 16 + d];
                float rv = sRbf[e * 16 + d];
                u[i][0]  += xv * wu.x; u[i][1]  += xv * wu.y;
                u[i][2]  += xv * wu.z; u[i][3]  += xv * wu.w;
                rr[i][0] += rv * wr.x; rr[i][1] += rv * wr.y;
                rr[i][2] += rv * wr.z; rr[i][3] += rv * wr.w;
            }
        }
        #pragma unroll
        for (int i = 0; i < 4; i++) {
            int e = et + 8 * i;
            int a = sIdx[e];
            if (a < 0) continue;
            float4 mm = ((const float4*)(m + (size_t)(e0 + e) * 128))[lane];
            float vx = (mm.x + ssilu(u[i][0])) * rr[i][0];
            float vy = (mm.y + ssilu(u[i][1])) * rr[i][1];
            float vz = (mm.z + ssilu(u[i][2])) * rr[i][2];
            float vw = (mm.w + ssilu(u[i][3])) * rr[i][3];
            float* dst = g_h + (size_t)a * 128 + lane * 4;
            asm volatile("red.global.add.v4.f32 [%0], {%1,%2,%3,%4};"
                         :: "l"(dst), "f"(vx), "f"(vy), "f"(vz), "f"(vw)
                         : "memory");
        }
    }
}

// ---------------- K4: atom output GEMM ----------------
// out = ssilu(g_h @ W_atom)   [N,128]
__global__ __launch_bounds__(256, 2) void k_atom_out(
    const float* __restrict__ Watom, float* __restrict__ out, int N)
{
    extern __shared__ float sm_[];
    float* sW = sm_;             // 16384 [k][j]
    float* sH = sm_ + 16384;     // 32*132

    int tid = threadIdx.x;
    for (int i = tid; i < 16384; i += 256) sW[i] = Watom[i];

    int ntiles = (N + 31) >> 5;
    int jt = tid & 31, et = tid >> 5;

    for (int tile = blockIdx.x; tile < ntiles; tile += gridDim.x) {
        int r0 = tile << 5;
        __syncthreads();
        for (int r = tid; r < 1024; r += 256) {
            int e = r >> 5, c = r & 31;
            float4 v = make_float4(0.f, 0.f, 0.f, 0.f);
            if (r0 + e < N) v = ((const float4*)(g_h + (size_t)(r0 + e) * 128))[c];
            *((float4*)&sH[e * 132 + c * 4]) = v;
        }
        __syncthreads();

        float acc[4][4];
        #pragma unroll
        for (int i = 0; i < 4; i++) {
            acc[i][0] = 0.f; acc[i][1] = 0.f; acc[i][2] = 0.f; acc[i][3] = 0.f;
        }
        #pragma unroll 4
        for (int k4 = 0; k4 < 32; k4++) {
            float4 mv[4];
            #pragma unroll
            for (int i = 0; i < 4; i++)
                mv[i] = *((float4*)&sH[(et * 4 + i) * 132 + k4 * 4]);
            #pragma unroll
            for (int kk = 0; kk < 4; kk++) {
                float4 w = *((float4*)&sW[(k4 * 4 + kk) * 128 + jt * 4]);
                #pragma unroll
                for (int i = 0; i < 4; i++) {
                    float mk = (kk == 0) ? mv[i].x : (kk == 1) ? mv[i].y
                             : (kk == 2) ? mv[i].z : mv[i].w;
                    acc[i][0] += mk * w.x;
                    acc[i][1] += mk * w.y;
                    acc[i][2] += mk * w.z;
                    acc[i][3] += mk * w.w;
                }
            }
        }
        #pragma unroll
        for (int i = 0; i < 4; i++) {
            int rrow = r0 + et * 4 + i;
            if (rrow < N) {
                float4 v;
                v.x = ssilu(acc[i][0]);
                v.y = ssilu(acc[i][1]);
                v.z = ssilu(acc[i][2]);
                v.w = ssilu(acc[i][3]);
                *((float4*)(out + (size_t)rrow * 128 + jt * 4)) = v;
            }
        }
        __syncthreads();
    }
}

extern "C" void kernel_launch(void* const* d_in, const int* in_sizes, int n_in,
                              void* d_out, int out_size) {
    const float* m     = (const float*)d_in[0];
    const float* rbf   = (const float*)d_in[1];
    const float* cbf   = (const float*)d_in[2];
    const int*   id3ba = (const int*)d_in[3];
    const int*   id3ca = (const int*)d_in[4];
    const int*   idxt  = (const int*)d_in[5];
    const float* Wba   = (const float*)d_in[6];
    const float* Wrbf  = (const float*)d_in[7];
    const float* Wdown = (const float*)d_in[8];
    const float* Wcbf  = (const float*)d_in[9];
    const float* Wup   = (const float*)d_in[10];
    const float* Wra   = (const float*)d_in[11];
    const float* Watom = (const float*)d_in[12];

    int E = in_sizes[0] / 128;
    int T = in_sizes[2] / 16;
    int N = out_size / 128;

    const int k1_smem = (16384 + 2048 + 16 * 132 + 32 * 132 + 512) * 4;
    const int k4_smem = (16384 + 32 * 132) * 4;
    cudaFuncSetAttribute(k_edge_down, cudaFuncAttributeMaxDynamicSharedMemorySize, k1_smem);
    cudaFuncSetAttribute(k_atom_out, cudaFuncAttributeMaxDynamicSharedMemorySize, k4_smem);

    k_zero<<<512, 256>>>((E * 16) / 4, (N * 128) / 4);
    k_edge_down<<<304, 256, k1_smem>>>(m, rbf, Wba, Wrbf, Wdown, E);
    k_triplet<<<(T + 255) / 256, 256>>>(cbf, id3ba, id3ca, Wcbf, T);
    k_edge_up<<<2048, 256>>>(m, rbf, idxt, Wup, Wra, E);
    k_atom_out<<<(N + 31) / 32, 256, k4_smem>>>(Watom, (float*)d_out, N);
}

// round 2
// speedup vs baseline: 1.0858x; 1.0858x over previous
#include <cuda_runtime.h>

#define SSCALE 1.6666666666666667f

__device__ __forceinline__ float ssilu(float x) {
    float e = __expf(-x);
    return SSCALE * __fdividef(x, 1.0f + e);
}

// ---- packed f32x2 helpers (Blackwell FFMA2) ----
__device__ __forceinline__ unsigned long long dup2(float x) {
    unsigned long long r;
    asm("mov.b64 %0, {%1, %1};" : "=l"(r) : "f"(x));
    return r;
}
__device__ __forceinline__ void up2(float& x, float& y, unsigned long long v) {
    asm("mov.b64 {%0, %1}, %2;" : "=f"(x), "=f"(y) : "l"(v));
}
#define FMA2(d, a, b) asm("fma.rn.f32x2 %0, %1, %2, %0;" : "+l"(d) : "l"(a), "l"(b))
#define MUL2(d, a, b) asm("mul.rn.f32x2 %0, %1, %2;" : "=l"(d) : "l"(a), "l"(b))

#define E_MAX 700000
#define N_MAX 40000

__device__ __align__(16) float g_xdown[(size_t)E_MAX * 16];
__device__ __align__(16) float g_xe[(size_t)E_MAX * 16];
__device__ __align__(16) float g_h[(size_t)N_MAX * 128];

// ---------------- K0: zero scratch ----------------
__global__ void k_zero(int n_xe4, int n_h4) {
    int i = blockIdx.x * blockDim.x + threadIdx.x;
    int stride = gridDim.x * blockDim.x;
    float4 z = make_float4(0.f, 0.f, 0.f, 0.f);
    for (int r = i; r < n_xe4; r += stride) ((float4*)g_xe)[r] = z;
    for (int r = i; r < n_h4; r += stride) ((float4*)g_h)[r] = z;
}

// ---------------- K1: edge dense + down projection (FFMA2, edge-pairs) ----
// x_ba = ssilu(m @ W_ba) * (rbf @ W_rbf);  g_xdown = x_ba @ W_down
// 64 edges/tile, 256 threads = 8 warps; warp wg handles edges wg*8..wg*8+7
// as 4 packed pairs; lane handles 4 j columns.
__global__ __launch_bounds__(256, 1) void k_edge_down(
    const float* __restrict__ m, const float* __restrict__ rbf,
    const float* __restrict__ Wba, const float* __restrict__ Wrbf,
    const float* __restrict__ Wdown, int E)
{
    extern __shared__ float sm_[];
    float* sWba  = sm_;              // [128][128] (k-major)
    float* sWrbf = sWba + 16384;     // [16][128]
    float* sWdT  = sWrbf + 2048;     // [16][132]  W_down transposed
    float* sMT   = sWdT + 2112;      // [128][64]  m transposed [k][e]
    float* sRbfT = sMT + 16384 / 2;  // [16][64]   rbf transposed [s][e]
    float* sXba  = sMT;              // [64][132]  aliases sMT+sRbfT region

    int tid = threadIdx.x;
    for (int i = tid; i < 16384; i += 256) sWba[i] = Wba[i];
    for (int i = tid; i < 2048; i += 256) sWrbf[i] = Wrbf[i];
    for (int i = tid; i < 2048; i += 256) {
        int d = i >> 7, j = i & 127;
        sWdT[d * 132 + j] = Wdown[j * 16 + d];
    }

    int lane = tid & 31, wg = tid >> 5;
    int jb = lane * 4, eb = wg * 8;
    int ntiles = (E + 63) >> 6;

    for (int tile = blockIdx.x; tile < ntiles; tile += gridDim.x) {
        int e0 = tile << 6;
        __syncthreads();   // previous tile done / weights loaded
        // load m tile transposed [k][e]
        for (int r = tid; r < 2048; r += 256) {
            int e = r & 63, k4 = r >> 6;
            float4 v = make_float4(0.f, 0.f, 0.f, 0.f);
            if (e0 + e < E) v = *(const float4*)(m + (size_t)(e0 + e) * 128 + k4 * 4);
            sMT[(k4 * 4 + 0) * 64 + e] = v.x;
            sMT[(k4 * 4 + 1) * 64 + e] = v.y;
            sMT[(k4 * 4 + 2) * 64 + e] = v.z;
            sMT[(k4 * 4 + 3) * 64 + e] = v.w;
        }
        {
            int e = tid & 63, sq = tid >> 6;
            float4 v = make_float4(0.f, 0.f, 0.f, 0.f);
            if (e0 + e < E) v = *(const float4*)(rbf + (size_t)(e0 + e) * 16 + sq * 4);
            sRbfT[(sq * 4 + 0) * 64 + e] = v.x;
            sRbfT[(sq * 4 + 1) * 64 + e] = v.y;
            sRbfT[(sq * 4 + 2) * 64 + e] = v.z;
            sRbfT[(sq * 4 + 3) * 64 + e] = v.w;
        }
        __syncthreads();

        // main mma: acc[ep][jj] packs (edge eb+2ep, eb+2ep+1) for column jb+jj
        unsigned long long acc[4][4];
        #pragma unroll
        for (int p = 0; p < 4; p++) {
            acc[p][0] = 0ull; acc[p][1] = 0ull; acc[p][2] = 0ull; acc[p][3] = 0ull;
        }
        #pragma unroll 8
        for (int k = 0; k < 128; k++) {
            float4 w = *(float4*)&sWba[k * 128 + jb];
            unsigned long long wd0 = dup2(w.x), wd1 = dup2(w.y),
                               wd2 = dup2(w.z), wd3 = dup2(w.w);
            ulonglong2 mA = *(ulonglong2*)&sMT[k * 64 + eb];
            ulonglong2 mB = *(ulonglong2*)&sMT[k * 64 + eb + 4];
            FMA2(acc[0][0], mA.x, wd0); FMA2(acc[0][1], mA.x, wd1);
            FMA2(acc[0][2], mA.x, wd2); FMA2(acc[0][3], mA.x, wd3);
            FMA2(acc[1][0], mA.y, wd0); FMA2(acc[1][1], mA.y, wd1);
            FMA2(acc[1][2], mA.y, wd2); FMA2(acc[1][3], mA.y, wd3);
            FMA2(acc[2][0], mB.x, wd0); FMA2(acc[2][1], mB.x, wd1);
            FMA2(acc[2][2], mB.x, wd2); FMA2(acc[2][3], mB.x, wd3);
            FMA2(acc[3][0], mB.y, wd0); FMA2(acc[3][1], mB.y, wd1);
            FMA2(acc[3][2], mB.y, wd2); FMA2(acc[3][3], mB.y, wd3);
        }

        // rbf modulation: rw = rbf @ W_rbf
        unsigned long long rw[4][4];
        #pragma unroll
        for (int p = 0; p < 4; p++) {
            rw[p][0] = 0ull; rw[p][1] = 0ull; rw[p][2] = 0ull; rw[p][3] = 0ull;
        }
        #pragma unroll 4
        for (int s = 0; s < 16; s++) {
            float4 w = *(float4*)&sWrbf[s * 128 + jb];
            unsigned long long wd0 = dup2(w.x), wd1 = dup2(w.y),
                               wd2 = dup2(w.z), wd3 = dup2(w.w);
            ulonglong2 rA = *(ulonglong2*)&sRbfT[s * 64 + eb];
            ulonglong2 rB = *(ulonglong2*)&sRbfT[s * 64 + eb + 4];
            FMA2(rw[0][0], rA.x, wd0); FMA2(rw[0][1], rA.x, wd1);
            FMA2(rw[0][2], rA.x, wd2); FMA2(rw[0][3], rA.x, wd3);
            FMA2(rw[1][0], rA.y, wd0); FMA2(rw[1][1], rA.y, wd1);
            FMA2(rw[1][2], rA.y, wd2); FMA2(rw[1][3], rA.y, wd3);
            FMA2(rw[2][0], rB.x, wd0); FMA2(rw[2][1], rB.x, wd1);
            FMA2(rw[2][2], rB.x, wd2); FMA2(rw[2][3], rB.x, wd3);
            FMA2(rw[3][0], rB.y, wd0); FMA2(rw[3][1], rB.y, wd1);
            FMA2(rw[3][2], rB.y, wd2); FMA2(rw[3][3], rB.y, wd3);
        }

        __syncthreads();   // all reads of sMT/sRbfT done; region becomes sXba
        #pragma unroll
        for (int ep = 0; ep < 4; ep++) {
            int e = eb + 2 * ep;
            #pragma unroll
            for (int jj = 0; jj < 4; jj++) {
                float a0, a1, r0, r1;
                up2(a0, a1, acc[ep][jj]);
                up2(r0, r1, rw[ep][jj]);
                sXba[(e + 0) * 132 + jb + jj] = ssilu(a0) * r0;
                sXba[(e + 1) * 132 + jb + jj] = ssilu(a1) * r1;
            }
        }
        __syncthreads();

        // down projection: 64e x 16d outputs
        for (int o = tid; o < 1024; o += 256) {
            int e = o >> 4, d = o & 15;
            unsigned long long s0 = 0ull, s1 = 0ull;
            #pragma unroll
            for (int j8 = 0; j8 < 16; j8++) {
                ulonglong2 xA = *(ulonglong2*)&sXba[e * 132 + j8 * 8];
                ulonglong2 xB = *(ulonglong2*)&sXba[e * 132 + j8 * 8 + 4];
                ulonglong2 wA = *(ulonglong2*)&sWdT[d * 132 + j8 * 8];
                ulonglong2 wB = *(ulonglong2*)&sWdT[d * 132 + j8 * 8 + 4];
                FMA2(s0, xA.x, wA.x); FMA2(s1, xA.y, wA.y);
                FMA2(s0, xB.x, wB.x); FMA2(s1, xB.y, wB.y);
            }
            float a, b, c, dd;
            up2(a, b, s0); up2(c, dd, s1);
            if (e0 + e < E) g_xdown[(size_t)(e0 + e) * 16 + d] = (a + b) + (c + dd);
        }
    }
}

// ---------------- K2: triplet gather/modulate/scatter (FFMA2) -------------
__global__ __launch_bounds__(256) void k_triplet(
    const float* __restrict__ cbf,
    const int* __restrict__ ba, const int* __restrict__ ca,
    const float* __restrict__ Wcbf, int T)
{
    __shared__ __align__(16) float sW[256];   // [s][d]
    int tid = threadIdx.x;
    sW[tid] = Wcbf[tid];
    __syncthreads();

    int t = blockIdx.x * 256 + tid;
    if (t >= T) return;

    float cv[16];
    {
        const float4* cp = (const float4*)(cbf + (size_t)t * 16);
        float4 a = cp[0], b = cp[1], c = cp[2], d = cp[3];
        cv[0]=a.x; cv[1]=a.y; cv[2]=a.z; cv[3]=a.w;
        cv[4]=b.x; cv[5]=b.y; cv[6]=b.z; cv[7]=b.w;
        cv[8]=c.x; cv[9]=c.y; cv[10]=c.z; cv[11]=c.w;
        cv[12]=d.x; cv[13]=d.y; cv[14]=d.z; cv[15]=d.w;
    }

    unsigned long long o2[8];
    #pragma unroll
    for (int q = 0; q < 8; q++) o2[q] = 0ull;
    #pragma unroll
    for (int s = 0; s < 16; s++) {
        unsigned long long cd = dup2(cv[s]);
        ulonglong2 wA = *(ulonglong2*)&sW[s * 16];
        ulonglong2 wB = *(ulonglong2*)&sW[s * 16 + 4];
        ulonglong2 wC = *(ulonglong2*)&sW[s * 16 + 8];
        ulonglong2 wD = *(ulonglong2*)&sW[s * 16 + 12];
        FMA2(o2[0], cd, wA.x); FMA2(o2[1], cd, wA.y);
        FMA2(o2[2], cd, wB.x); FMA2(o2[3], cd, wB.y);
        FMA2(o2[4], cd, wC.x); FMA2(o2[5], cd, wC.y);
        FMA2(o2[6], cd, wD.x); FMA2(o2[7], cd, wD.y);
    }

    int b = ba[t], a = ca[t];
    const ulonglong2* xd = (const ulonglong2*)(g_xdown + (size_t)b * 16);
    float* dst = g_xe + (size_t)a * 16;
    ulonglong2 x01 = xd[0], x23 = xd[1], x45 = xd[2], x67 = xd[3];
    unsigned long long p0, p1;
    float v0, v1, v2, v3;

    MUL2(p0, o2[0], x01.x); MUL2(p1, o2[1], x01.y);
    up2(v0, v1, p0); up2(v2, v3, p1);
    asm volatile("red.global.add.v4.f32 [%0], {%1,%2,%3,%4};"
                 :: "l"(dst), "f"(v0), "f"(v1), "f"(v2), "f"(v3) : "memory");
    MUL2(p0, o2[2], x23.x); MUL2(p1, o2[3], x23.y);
    up2(v0, v1, p0); up2(v2, v3, p1);
    asm volatile("red.global.add.v4.f32 [%0], {%1,%2,%3,%4};"
                 :: "l"(dst + 4), "f"(v0), "f"(v1), "f"(v2), "f"(v3) : "memory");
    MUL2(p0, o2[4], x45.x); MUL2(p1, o2[5], x45.y);
    up2(v0, v1, p0); up2(v2, v3, p1);
    asm volatile("red.global.add.v4.f32 [%0], {%1,%2,%3,%4};"
                 :: "l"(dst + 8), "f"(v0), "f"(v1), "f"(v2), "f"(v3) : "memory");
    MUL2(p0, o2[6], x67.x); MUL2(p1, o2[7], x67.y);
    up2(v0, v1, p0); up2(v2, v3, p1);
    asm volatile("red.global.add.v4.f32 [%0], {%1,%2,%3,%4};"
                 :: "l"(dst + 12), "f"(v0), "f"(v1), "f"(v2), "f"(v3) : "memory");
}

// ---------------- K3: edge up-projection + atom scatter (occ 4) ----------
__global__ __launch_bounds__(256, 4) void k_edge_up(
    const float* __restrict__ m, const float* __restrict__ rbf,
    const int* __restrict__ idxt,
    const float* __restrict__ Wup, const float* __restrict__ Wra, int E)
{
    __shared__ __align__(16) float sWup[2048];   // [d][j]
    __shared__ __align__(16) float sWra[2048];   // [s][j]
    __shared__ __align__(16) float sXe[256];     // [16][16]
    __shared__ __align__(16) float sRb[256];     // [16][16]
    __shared__ int sIdx[16];

    int tid = threadIdx.x;
    for (int i = tid; i < 2048; i += 256) { sWup[i] = Wup[i]; sWra[i] = Wra[i]; }

    int lane = tid & 31, et = tid >> 5;
    int jb = lane * 4;
    int ntiles = (E + 15) >> 4;

    for (int tile = blockIdx.x; tile < ntiles; tile += gridDim.x) {
        int e0 = tile << 4;
        __syncthreads();
        if (tid < 64) {
            int e = tid >> 2, q = tid & 3;
            float4 vx = make_float4(0.f, 0.f, 0.f, 0.f), vr = vx;
            if (e0 + e < E) {
                vx = *(const float4*)(g_xe + (size_t)(e0 + e) * 16 + q * 4);
                vr = *(const float4*)(rbf + (size_t)(e0 + e) * 16 + q * 4);
            }
            *(float4*)&sXe[e * 16 + q * 4] = vx;
            *(float4*)&sRb[e * 16 + q * 4] = vr;
        }
        if (tid < 16) sIdx[tid] = (e0 + tid < E) ? idxt[e0 + tid] : -1;
        __syncthreads();

        unsigned long long u2[2][2], rr2[2][2];
        u2[0][0]=u2[0][1]=u2[1][0]=u2[1][1]=0ull;
        rr2[0][0]=rr2[0][1]=rr2[1][0]=rr2[1][1]=0ull;
        #pragma unroll
        for (int d = 0; d < 16; d++) {
            ulonglong2 wu = *(ulonglong2*)&sWup[d * 128 + jb];
            ulonglong2 wr = *(ulonglong2*)&sWra[d * 128 + jb];
            #pragma unroll
            for (int i = 0; i < 2; i++) {
                int e = et * 2 + i;
                unsigned long long xd = dup2(sXe[e * 16 + d]);
                unsigned long long rd = dup2(sRb[e * 16 + d]);
                FMA2(u2[i][0], xd, wu.x);  FMA2(u2[i][1], xd, wu.y);
                FMA2(rr2[i][0], rd, wr.x); FMA2(rr2[i][1], rd, wr.y);
            }
        }
        #pragma unroll
        for (int i = 0; i < 2; i++) {
            int e = et * 2 + i;
            int a = sIdx[e];
            if (a < 0) continue;
            float4 mm = *(const float4*)(m + (size_t)(e0 + e) * 128 + jb);
            float ua, ub, uc, ud, ra, rb, rc, rd;
            up2(ua, ub, u2[i][0]); up2(uc, ud, u2[i][1]);
            up2(ra, rb, rr2[i][0]); up2(rc, rd, rr2[i][1]);
            float vx = (mm.x + ssilu(ua)) * ra;
            float vy = (mm.y + ssilu(ub)) * rb;
            float vz = (mm.z + ssilu(uc)) * rc;
            float vw = (mm.w + ssilu(ud)) * rd;
            float* dst = g_h + (size_t)a * 128 + jb;
            asm volatile("red.global.add.v4.f32 [%0], {%1,%2,%3,%4};"
                         :: "l"(dst), "f"(vx), "f"(vy), "f"(vz), "f"(vw)
                         : "memory");
        }
    }
}

// ---------------- K4: atom output GEMM ----------------
__global__ __launch_bounds__(256, 2) void k_atom_out(
    const float* __restrict__ Watom, float* __restrict__ out, int N)
{
    extern __shared__ float sm_[];
    float* sW = sm_;             // 16384 [k][j]
    float* sH = sm_ + 16384;     // 32*132

    int tid = threadIdx.x;
    for (int i = tid; i < 16384; i += 256) sW[i] = Watom[i];

    int ntiles = (N + 31) >> 5;
    int jt = tid & 31, et = tid >> 5;

    for (int tile = blockIdx.x; tile < ntiles; tile += gridDim.x) {
        int r0 = tile << 5;
        __syncthreads();
        for (int r = tid; r < 1024; r += 256) {
            int e = r >> 5, c = r & 31;
            float4 v = make_float4(0.f, 0.f, 0.f, 0.f);
            if (r0 + e < N) v = ((const float4*)(g_h + (size_t)(r0 + e) * 128))[c];
            *((float4*)&sH[e * 132 + c * 4]) = v;
        }
        __syncthreads();

        float acc[4][4];
        #pragma unroll
        for (int i = 0; i < 4; i++) {
            acc[i][0] = 0.f; acc[i][1] = 0.f; acc[i][2] = 0.f; acc[i][3] = 0.f;
        }
        #pragma unroll 4
        for (int k4 = 0; k4 < 32; k4++) {
            float4 mv[4];
            #pragma unroll
            for (int i = 0; i < 4; i++)
                mv[i] = *((float4*)&sH[(et * 4 + i) * 132 + k4 * 4]);
            #pragma unroll
            for (int kk = 0; kk < 4; kk++) {
                float4 w = *((float4*)&sW[(k4 * 4 + kk) * 128 + jt * 4]);
                #pragma unroll
                for (int i = 0; i < 4; i++) {
                    float mk = (kk == 0) ? mv[i].x : (kk == 1) ? mv[i].y
                             : (kk == 2) ? mv[i].z : mv[i].w;
                    acc[i][0] += mk * w.x;
                    acc[i][1] += mk * w.y;
                    acc[i][2] += mk * w.z;
                    acc[i][3] += mk * w.w;
                }
            }
        }
        #pragma unroll
        for (int i = 0; i < 4; i++) {
            int rrow = r0 + et * 4 + i;
            if (rrow < N) {
                float4 v;
                v.x = ssilu(acc[i][0]);
                v.y = ssilu(acc[i][1]);
                v.z = ssilu(acc[i][2]);
                v.w = ssilu(acc[i][3]);
                *((float4*)(out + (size_t)rrow * 128 + jt * 4)) = v;
            }
        }
        __syncthreads();
    }
}

extern "C" void kernel_launch(void* const* d_in, const int* in_sizes, int n_in,
                              void* d_out, int out_size) {
    const float* m     = (const float*)d_in[0];
    const float* rbf   = (const float*)d_in[1];
    const float* cbf   = (const float*)d_in[2];
    const int*   id3ba = (const int*)d_in[3];
    const int*   id3ca = (const int*)d_in[4];
    const int*   idxt  = (const int*)d_in[5];
    const float* Wba   = (const float*)d_in[6];
    const float* Wrbf  = (const float*)d_in[7];
    const float* Wdown = (const float*)d_in[8];
    const float* Wcbf  = (const float*)d_in[9];
    const float* Wup   = (const float*)d_in[10];
    const float* Wra   = (const float*)d_in[11];
    const float* Watom = (const float*)d_in[12];

    int E = in_sizes[0] / 128;
    int T = in_sizes[2] / 16;
    int N = out_size / 128;

    // k_edge_down smem: weights 20544 + union(sMT 8192 + sRbfT 1024) floats
    const int k1_smem = (16384 + 2048 + 2112 + 8192 + 1024) * 4;
    const int k4_smem = (16384 + 32 * 132) * 4;
    cudaFuncSetAttribute(k_edge_down, cudaFuncAttributeMaxDynamicSharedMemorySize, k1_smem);
    cudaFuncSetAttribute(k_atom_out, cudaFuncAttributeMaxDynamicSharedMemorySize, k4_smem);

    k_zero<<<512, 256>>>((E * 16) / 4, (N * 128) / 4);
    k_edge_down<<<148, 256, k1_smem>>>(m, rbf, Wba, Wrbf, Wdown, E);
    k_triplet<<<(T + 255) / 256, 256>>>(cbf, id3ba, id3ca, Wcbf, T);
    k_edge_up<<<4096, 256>>>(m, rbf, idxt, Wup, Wra, E);
    k_atom_out<<<(N + 31) / 32, 256, k4_smem>>>(Watom, (float*)d_out, N);
}